// round 15
// baseline (speedup 1.0000x reference)
#include <cuda_runtime.h>
#include <cuda_fp16.h>
#include <cstdint>

#define BB 4
#define TT 4096
#define CC 768
#define HH 64
#define M_TOT (BB*TT)
#define KS 4
#define NQT 64            // 64-row q-tiles per batch

// ---------------- mma / ldmatrix helpers ----------------
__device__ __forceinline__ void mma16(float c[4], uint32_t a0, uint32_t a1,
                                      uint32_t a2, uint32_t a3,
                                      uint32_t b0, uint32_t b1) {
    asm volatile(
        "mma.sync.aligned.m16n8k16.row.col.f32.f16.f16.f32 "
        "{%0,%1,%2,%3}, {%4,%5,%6,%7}, {%8,%9}, {%0,%1,%2,%3};"
        : "+f"(c[0]), "+f"(c[1]), "+f"(c[2]), "+f"(c[3])
        : "r"(a0), "r"(a1), "r"(a2), "r"(a3), "r"(b0), "r"(b1));
}
__device__ __forceinline__ void ldsm4(uint32_t* r, uint32_t addr) {
    asm volatile("ldmatrix.sync.aligned.m8n8.x4.shared.b16 {%0,%1,%2,%3}, [%4];"
        : "=r"(r[0]), "=r"(r[1]), "=r"(r[2]), "=r"(r[3]) : "r"(addr));
}
__device__ __forceinline__ float ex2(float x) {
    float r;
    asm("ex2.approx.f32 %0, %1;" : "=f"(r) : "f"(x));
    return r;
}
__device__ __forceinline__ uint32_t smem_u32(const void* p) {
    uint32_t a;
    asm("{ .reg .u64 t; cvta.to.shared.u64 t, %1; cvt.u32.u64 %0, t; }" : "=r"(a) : "l"(p));
    return a;
}
#define CP16(dst, src) asm volatile("cp.async.cg.shared.global [%0], [%1], 16;" :: "r"(dst), "l"(src))
#define CP_COMMIT()    asm volatile("cp.async.commit_group;" ::: "memory")
#define CP_WAIT0()     asm volatile("cp.async.wait_group 0;" ::: "memory")

// ---------------- global scratch ----------------
__device__ __half g_wT16[3*HH*CC];            // W^T fp16: [mat][n][k]; Wq pre-scaled
__device__ __half g_q16[M_TOT*HH];            // pre-scaled by log2(e)/8 (via Wq)
__device__ __half g_k16[M_TOT*HH];
__device__ __half g_vT16[(size_t)BB*HH*TT];   // V transposed: [b][h][s]
__device__ float  g_pacc[(size_t)BB*NQT*KS*64*64];   // fp32 partials
__device__ float  g_pl[BB*NQT*KS*64];

// ---------------------------------------------------------------------------
// Kernel 0: convert + transpose W -> g_wT16[mat][n][k]; fold log2(e)/8 into Wq.
// ---------------------------------------------------------------------------
__global__ __launch_bounds__(256)
void cvtw_kernel(const float* __restrict__ Wk,
                 const float* __restrict__ Wq,
                 const float* __restrict__ Wv) {
    const int mat = blockIdx.y;
    const float* W = (mat == 0) ? Wk : ((mat == 1) ? Wq : Wv);
    const float scale = (mat == 1) ? 0.18033688011112042f : 1.0f;
    for (int idx = blockIdx.x * 256 + threadIdx.x; idx < CC * HH; idx += gridDim.x * 256) {
        int k = idx >> 6, n = idx & 63;
        g_wT16[(mat * HH + n) * CC + k] = __float2half(W[idx] * scale);
    }
}

// ---------------------------------------------------------------------------
// Kernel 1: QKV projection, fp16 m16n8k16 + ldmatrix, reading x in fp32
// directly (conversion fused into staging — no cvtx prepass).
// CTA tile 64x64, kc=64, 8 warps of 16x32. X register-prefetched fp32 and
// cvt+STS'd into the spare fp16 buffer; W^T via cp.async. 1 sync/chunk.
// smem u32: XB[2][2048] | WB[2][2048] = 32KB.
// ---------------------------------------------------------------------------
#define PROJ_SMEM (8192 * 4)

__global__ __launch_bounds__(256, 3)
void proj_kernel(const float* __restrict__ x) {
    extern __shared__ uint32_t smu[];
    const uint32_t sb = smem_u32(smu);
    const int XB0 = 0;            // [2][2048 u32]
    const int WB0 = 4096;         // [2][2048 u32]

    const int mat  = blockIdx.y;
    const int m0   = blockIdx.x * 64;
    const int tid  = threadIdx.x;
    const int wid  = tid >> 5;
    const int lane = tid & 31;
    const int g    = lane >> 2;
    const int t    = lane & 3;
    const int ms   = wid >> 1;           // 0..3: 16-row slab
    const int nb   = (wid & 1) * 32;     // 0/32

    // ldmatrix lane params
    const int lsw  = (lane & 7) << 2;
    const int am   = lane >> 3;
    const int akh  = (am >> 1) << 2;
    const int arow0 = ms * 16 + ((am & 1) << 3) + (lane & 7);
    const int bkh  = ((lane >> 3) & 1) << 2;
    const int brow0 = nb + ((lane >> 4) << 3) + (lane & 7);

    const __half* wp = g_wT16 + (size_t)mat * HH * CC;

    // X staging: 64 rows, 4 thr/row, 16 floats each -> 2 swizzled 16B chunks
    const int xrow = tid >> 2;
    const int xc0  = (tid & 3) * 2;      // first of two 8-half chunks
    const int xsw  = (xrow & 7) << 2;
    const float* xsrc = x + (size_t)(m0 + xrow) * CC + (tid & 3) * 16;

    float oc[4][4];
#pragma unroll
    for (int i = 0; i < 4; i++)
#pragma unroll
        for (int j = 0; j < 4; j++) oc[i][j] = 0.f;

    // prologue: X(0) LDG+cvt+STS; W(0) cp.async
    {
#pragma unroll
        for (int h = 0; h < 2; h++) {
            float4 a = *(const float4*)(xsrc + h * 8);
            float4 b = *(const float4*)(xsrc + h * 8 + 4);
            __half2 h0 = __floats2half2_rn(a.x, a.y);
            __half2 h1 = __floats2half2_rn(a.z, a.w);
            __half2 h2 = __floats2half2_rn(b.x, b.y);
            __half2 h3 = __floats2half2_rn(b.z, b.w);
            uint4 o = make_uint4(*(uint32_t*)&h0, *(uint32_t*)&h1,
                                 *(uint32_t*)&h2, *(uint32_t*)&h3);
            *(uint4*)&smu[XB0 + xrow * 32 + (((xc0 + h) * 4) ^ xsw)] = o;
        }
#pragma unroll
        for (int it = 0; it < 2; it++) {
            int idx = it * 256 + tid;
            int wrow = idx >> 3;
            int wc   = idx & 7;
            uint32_t sw = (uint32_t)((wc * 4) ^ ((wrow & 7) << 2));
            CP16(sb + (WB0 + wrow * 32 + sw) * 4, wp + (size_t)wrow * CC + wc * 8);
        }
        CP_COMMIT();
    }
    CP_WAIT0();
    __syncthreads();

    int buf = 0;
    for (int k0 = 0; k0 < CC; k0 += 64) {
        const bool pre = (k0 + 64 < CC);
        float4 pxa[2], pxb[2];
        if (pre) {
#pragma unroll
            for (int h = 0; h < 2; h++) {
                pxa[h] = *(const float4*)(xsrc + k0 + 64 + h * 8);
                pxb[h] = *(const float4*)(xsrc + k0 + 64 + h * 8 + 4);
            }
            const int wb = WB0 + (buf ^ 1) * 2048;
#pragma unroll
            for (int it = 0; it < 2; it++) {
                int idx = it * 256 + tid;
                int wrow = idx >> 3;
                int wc   = idx & 7;
                uint32_t sw = (uint32_t)((wc * 4) ^ ((wrow & 7) << 2));
                CP16(sb + (wb + wrow * 32 + sw) * 4,
                     wp + (size_t)wrow * CC + k0 + 64 + wc * 8);
            }
            CP_COMMIT();
        }

        const int xb = XB0 + buf * 2048;
        const int wb = WB0 + buf * 2048;
#pragma unroll
        for (int kk = 0; kk < 4; kk++) {
            uint32_t av[4], bv[8];
            uint32_t cuA = (uint32_t)((kk * 8 + akh) ^ lsw);
            ldsm4(av, sb + (xb + arow0 * 32 + cuA) * 4);
            uint32_t cuB = (uint32_t)((kk * 8 + bkh) ^ lsw);
            ldsm4(bv,     sb + (wb + brow0 * 32 + cuB) * 4);
            ldsm4(bv + 4, sb + (wb + (brow0 + 16) * 32 + cuB) * 4);
#pragma unroll
            for (int nt = 0; nt < 4; nt++)
                mma16(oc[nt], av[0], av[1], av[2], av[3], bv[2*nt], bv[2*nt+1]);
        }

        if (pre) {
            // store next X into the other buffer (no sync needed: disjoint buf)
            const int xn = XB0 + (buf ^ 1) * 2048;
#pragma unroll
            for (int h = 0; h < 2; h++) {
                __half2 h0 = __floats2half2_rn(pxa[h].x, pxa[h].y);
                __half2 h1 = __floats2half2_rn(pxa[h].z, pxa[h].w);
                __half2 h2 = __floats2half2_rn(pxb[h].x, pxb[h].y);
                __half2 h3 = __floats2half2_rn(pxb[h].z, pxb[h].w);
                uint4 o = make_uint4(*(uint32_t*)&h0, *(uint32_t*)&h1,
                                     *(uint32_t*)&h2, *(uint32_t*)&h3);
                *(uint4*)&smu[xn + xrow * 32 + (((xc0 + h) * 4) ^ xsw)] = o;
            }
        }
        CP_WAIT0();
        __syncthreads();
        buf ^= 1;
    }

    if (mat < 2) {
        __half* out16 = (mat == 0) ? g_k16 : g_q16;
        int r0g = m0 + ms * 16 + g;
#pragma unroll
        for (int nt = 0; nt < 4; nt++) {
            int col = nb + nt * 8 + 2 * t;
            __half2 h0 = __floats2half2_rn(oc[nt][0], oc[nt][1]);
            __half2 h1 = __floats2half2_rn(oc[nt][2], oc[nt][3]);
            *(__half2*)&out16[(size_t)r0g * HH + col]       = h0;
            *(__half2*)&out16[(size_t)(r0g + 8) * HH + col] = h1;
        }
    } else {
        // v: transpose through smem -> g_vT16[b][h][s] coalesced
        __syncthreads();
        __half* Vt = (__half*)smu;   // [64 h][80 s] halves (stride 80 -> 16B-aligned rows)
        int s0l = ms * 16 + g;       // local s rows s0l, s0l+8
#pragma unroll
        for (int nt = 0; nt < 4; nt++) {
            int col = nb + nt * 8 + 2 * t;
            Vt[col * 80 + s0l]           = __float2half(oc[nt][0]);
            Vt[(col + 1) * 80 + s0l]     = __float2half(oc[nt][1]);
            Vt[col * 80 + s0l + 8]       = __float2half(oc[nt][2]);
            Vt[(col + 1) * 80 + s0l + 8] = __float2half(oc[nt][3]);
        }
        __syncthreads();
        const int batch = m0 >> 12;
        const int s0    = m0 & (TT - 1);
        const int row = tid >> 2;           // h: 0..63
        const int seg = tid & 3;
#pragma unroll
        for (int it = 0; it < 2; it++) {
            int off = seg * 16 + it * 8;    // halves within 64-half row
            uint4 v = *(uint4*)&Vt[row * 80 + off];
            *(uint4*)&g_vT16[((size_t)(batch * HH + row)) * TT + s0 + off] = v;
        }
    }
}

// ---------------------------------------------------------------------------
// Kernel 2: fp16 flash attention partials (ldmatrix). Post-softmax sync is a
// 64-thread named barrier (P exchanged only within the (ms, nh)-warp pair).
// ---------------------------------------------------------------------------
#define KB_OFF 0
#define VB_OFF 4096
#define QP_OFF 8192
#define LB_OFF 10240
#define ATTN_SMEM ((10240 + 128) * 4)

__global__ __launch_bounds__(256, 3)
void attn_kernel() {
    extern __shared__ uint32_t smu[];
    const uint32_t sb = smem_u32(smu);

    const int tid  = threadIdx.x;
    const int wid  = tid >> 5;
    const int lane = tid & 31;
    const int g    = lane >> 2;
    const int t    = lane & 3;
    const int ms   = wid >> 1;
    const int nh   = wid & 1;
    const int nb   = nh * 32;
    const int r0   = ms * 16 + g;
    const int gx   = g << 2;
    const int barid = ms + 1;

    // ldmatrix lane params
    const int lsw  = (lane & 7) << 2;
    const int bkh  = ((lane >> 3) & 1) << 2;
    const int brow0 = nb + ((lane >> 4) << 3) + (lane & 7);
    const int am   = lane >> 3;
    const int akh  = (am >> 1) << 2;
    const int arow0 = ms * 16 + ((am & 1) << 3) + (lane & 7);

    const int b     = blockIdx.y;
    const int qt    = NQT - 1 - (blockIdx.x >> 2);
    const int split = blockIdx.x & (KS - 1);
    const int q0    = qt * 64;
    const int nch   = qt + 1;
    const int lo    = (split * nch) / KS;
    const int hi    = ((split + 1) * nch) / KS;
    const size_t slot = (size_t)(b * NQT + qt) * KS + split;
    float* pa = g_pacc + slot * 4096;

    if (lo >= hi) {
        float4 z = make_float4(0.f, 0.f, 0.f, 0.f);
        for (int e = tid; e < 1024; e += 256) ((float4*)pa)[e] = z;
        if (tid < 64) g_pl[slot * 64 + tid] = 0.f;
        return;
    }

    const __half* qp  = g_q16 + (size_t)b * TT * HH;
    const __half* kp  = g_k16 + (size_t)b * TT * HH;
    const __half* vtp = g_vT16 + (size_t)b * HH * TT;

    const int srow = tid >> 2;
    const int sc4  = tid & 3;

    {
        const int s0 = lo * 64;
#pragma unroll
        for (int it = 0; it < 2; it++) {
            int c = sc4 + 4 * it;
            uint32_t sw = (uint32_t)((c * 4) ^ ((srow & 7) << 2));
            CP16(sb + (KB_OFF + srow * 32 + sw) * 4, kp + (size_t)(s0 + srow) * HH + c * 8);
            CP16(sb + (VB_OFF + srow * 32 + sw) * 4, vtp + (size_t)srow * TT + s0 + c * 8);
            CP16(sb + (QP_OFF + srow * 32 + sw) * 4, qp + (size_t)(q0 + srow) * HH + c * 8);
        }
        CP_COMMIT();
    }
    CP_WAIT0();
    __syncthreads();

    uint32_t qa[4][4];
#pragma unroll
    for (int kk = 0; kk < 4; kk++) {
        uint32_t cu = (uint32_t)((kk * 8 + akh) ^ lsw);
        ldsm4(qa[kk], sb + (QP_OFF + arow0 * 32 + cu) * 4);
    }
    __syncthreads();

    float oc[4][4];
#pragma unroll
    for (int i = 0; i < 4; i++)
#pragma unroll
        for (int j = 0; j < 4; j++) oc[i][j] = 0.f;
    float lr0 = 0.f, lr1 = 0.f;

    int buf = 0;
    for (int ck = lo; ck < hi; ck++) {
        if (ck + 1 < hi) {
            const int s1 = (ck + 1) * 64;
            const int kb = KB_OFF + (buf ^ 1) * 2048;
            const int vb = VB_OFF + (buf ^ 1) * 2048;
#pragma unroll
            for (int it = 0; it < 2; it++) {
                int c = sc4 + 4 * it;
                uint32_t sw = (uint32_t)((c * 4) ^ ((srow & 7) << 2));
                CP16(sb + (kb + srow * 32 + sw) * 4, kp + (size_t)(s1 + srow) * HH + c * 8);
                CP16(sb + (vb + srow * 32 + sw) * 4, vtp + (size_t)srow * TT + s1 + c * 8);
            }
        }
        CP_COMMIT();

        const int kb = KB_OFF + buf * 2048;
        const int vb = VB_OFF + buf * 2048;

        // GEMM1: S = Q x K^T
        float sc[4][4];
#pragma unroll
        for (int i = 0; i < 4; i++)
#pragma unroll
            for (int j = 0; j < 4; j++) sc[i][j] = 0.f;
#pragma unroll
        for (int kk = 0; kk < 4; kk++) {
            uint32_t bv[8];
            uint32_t cu = (uint32_t)((kk * 8 + bkh) ^ lsw);
            ldsm4(bv,     sb + (kb + brow0 * 32 + cu) * 4);
            ldsm4(bv + 4, sb + (kb + (brow0 + 16) * 32 + cu) * 4);
#pragma unroll
            for (int nt = 0; nt < 4; nt++)
                mma16(sc[nt], qa[kk][0], qa[kk][1], qa[kk][2], qa[kk][3],
                      bv[2*nt], bv[2*nt+1]);
        }

        // softmax
        const bool diag = (ck == qt);
#pragma unroll
        for (int nt = 0; nt < 4; nt++) {
            int cl = nb + nt * 8 + 2 * t;
            float p0 = ex2(sc[nt][0]);
            float p1 = ex2(sc[nt][1]);
            float p2 = ex2(sc[nt][2]);
            float p3 = ex2(sc[nt][3]);
            if (diag) {
                if (cl > r0)         p0 = 0.f;
                if (cl + 1 > r0)     p1 = 0.f;
                if (cl > r0 + 8)     p2 = 0.f;
                if (cl + 1 > r0 + 8) p3 = 0.f;
            }
            __half2 h01 = __floats2half2_rn(p0, p1);
            __half2 h23 = __floats2half2_rn(p2, p3);
            float2 f01 = __half22float2(h01);
            float2 f23 = __half22float2(h23);
            lr0 += f01.x + f01.y;
            lr1 += f23.x + f23.y;
            int j = (nb >> 1) + nt * 4 + t;
            smu[QP_OFF + r0 * 32 + (j ^ gx)]       = *(uint32_t*)&h01;
            smu[QP_OFF + (r0 + 8) * 32 + (j ^ gx)] = *(uint32_t*)&h23;
        }
        // P exchange only within the (ms) warp pair -> 64-thread named barrier
        asm volatile("bar.sync %0, 64;" :: "r"(barid) : "memory");

        // GEMM2: O += P x V
#pragma unroll
        for (int kk = 0; kk < 4; kk++) {
            uint32_t av[4], bv[8];
            uint32_t cuA = (uint32_t)((kk * 8 + akh) ^ lsw);
            ldsm4(av, sb + (QP_OFF + arow0 * 32 + cuA) * 4);
            uint32_t cuB = (uint32_t)((kk * 8 + bkh) ^ lsw);
            ldsm4(bv,     sb + (vb + brow0 * 32 + cuB) * 4);
            ldsm4(bv + 4, sb + (vb + (brow0 + 16) * 32 + cuB) * 4);
#pragma unroll
            for (int nt = 0; nt < 4; nt++)
                mma16(oc[nt], av[0], av[1], av[2], av[3], bv[2*nt], bv[2*nt+1]);
        }

        CP_WAIT0();
        __syncthreads();
        buf ^= 1;
    }

    float* lbuf = (float*)(smu + LB_OFF);
    lr0 += __shfl_xor_sync(0xffffffffu, lr0, 1);
    lr0 += __shfl_xor_sync(0xffffffffu, lr0, 2);
    lr1 += __shfl_xor_sync(0xffffffffu, lr1, 1);
    lr1 += __shfl_xor_sync(0xffffffffu, lr1, 2);
    if (t == 0) {
        lbuf[nh * 64 + r0]     = lr0;
        lbuf[nh * 64 + r0 + 8] = lr1;
    }
    __syncthreads();

#pragma unroll
    for (int nt = 0; nt < 4; nt++) {
        int col = nb + nt * 8 + 2 * t;
        *(float2*)&pa[r0 * 64 + col]       = make_float2(oc[nt][0], oc[nt][1]);
        *(float2*)&pa[(r0 + 8) * 64 + col] = make_float2(oc[nt][2], oc[nt][3]);
    }
    if (tid < 64) g_pl[slot * 64 + tid] = lbuf[tid] + lbuf[64 + tid];
}

// ---------------------------------------------------------------------------
// Kernel 3: merge key-split partials (plain sums) and normalize.
// ---------------------------------------------------------------------------
__global__ __launch_bounds__(256)
void combine_kernel(float* __restrict__ out) {
    const int qt = blockIdx.x;
    const int b  = blockIdx.y;
    const int tid = threadIdx.x;
    const size_t base = (size_t)(b * NQT + qt) * KS;

    __shared__ float ls[64];
    if (tid < 64) {
        float s = 0.f;
#pragma unroll
        for (int sp = 0; sp < KS; sp++) s += g_pl[(base + sp) * 64 + tid];
        ls[tid] = 1.0f / s;
    }
    __syncthreads();

    for (int e = tid; e < 1024; e += 256) {
        const int row = e >> 4;
        float4 a = make_float4(0.f, 0.f, 0.f, 0.f);
#pragma unroll
        for (int sp = 0; sp < KS; sp++) {
            float4 v = ((const float4*)(g_pacc + (base + sp) * 4096))[e];
            a.x += v.x; a.y += v.y; a.z += v.z; a.w += v.w;
        }
        const float inv = ls[row];
        a.x *= inv; a.y *= inv; a.z *= inv; a.w *= inv;
        *(float4*)&out[((size_t)b * TT + qt * 64 + row) * HH + (e & 15) * 4] = a;
    }
}

extern "C" void kernel_launch(void* const* d_in, const int* in_sizes, int n_in,
                              void* d_out, int out_size) {
    const float* x  = (const float*)d_in[0];
    const float* Wk = (const float*)d_in[1];
    const float* Wq = (const float*)d_in[2];
    const float* Wv = (const float*)d_in[3];
    float* out = (float*)d_out;

    cvtw_kernel<<<dim3(8, 3), 256>>>(Wk, Wq, Wv);

    cudaFuncSetAttribute(proj_kernel,
                         cudaFuncAttributeMaxDynamicSharedMemorySize, PROJ_SMEM);
    proj_kernel<<<dim3(M_TOT / 64, 3), 256, PROJ_SMEM>>>(x);

    cudaFuncSetAttribute(attn_kernel,
                         cudaFuncAttributeMaxDynamicSharedMemorySize, ATTN_SMEM);
    attn_kernel<<<dim3(NQT * KS, BB), 256, ATTN_SMEM>>>();

    combine_kernel<<<dim3(NQT, BB), 256>>>(out);
}

// round 16
// speedup vs baseline: 1.1039x; 1.1039x over previous
#include <cuda_runtime.h>
#include <cuda_fp16.h>
#include <cstdint>

#define BB 4
#define TT 4096
#define CC 768
#define HH 64
#define M_TOT (BB*TT)
#define KS 4
#define NQT 64            // 64-row q-tiles per batch

// ---------------- mma / ldmatrix helpers ----------------
__device__ __forceinline__ void mma16(float c[4], uint32_t a0, uint32_t a1,
                                      uint32_t a2, uint32_t a3,
                                      uint32_t b0, uint32_t b1) {
    asm volatile(
        "mma.sync.aligned.m16n8k16.row.col.f32.f16.f16.f32 "
        "{%0,%1,%2,%3}, {%4,%5,%6,%7}, {%8,%9}, {%0,%1,%2,%3};"
        : "+f"(c[0]), "+f"(c[1]), "+f"(c[2]), "+f"(c[3])
        : "r"(a0), "r"(a1), "r"(a2), "r"(a3), "r"(b0), "r"(b1));
}
__device__ __forceinline__ void ldsm4(uint32_t* r, uint32_t addr) {
    asm volatile("ldmatrix.sync.aligned.m8n8.x4.shared.b16 {%0,%1,%2,%3}, [%4];"
        : "=r"(r[0]), "=r"(r[1]), "=r"(r[2]), "=r"(r[3]) : "r"(addr));
}
__device__ __forceinline__ float ex2(float x) {
    float r;
    asm("ex2.approx.f32 %0, %1;" : "=f"(r) : "f"(x));
    return r;
}
__device__ __forceinline__ uint32_t smem_u32(const void* p) {
    uint32_t a;
    asm("{ .reg .u64 t; cvta.to.shared.u64 t, %1; cvt.u32.u64 %0, t; }" : "=r"(a) : "l"(p));
    return a;
}
#define CP16(dst, src) asm volatile("cp.async.cg.shared.global [%0], [%1], 16;" :: "r"(dst), "l"(src))
#define CP_COMMIT()    asm volatile("cp.async.commit_group;" ::: "memory")
#define CP_WAIT0()     asm volatile("cp.async.wait_group 0;" ::: "memory")

// ---------------- global scratch ----------------
__device__ __half g_x16[(size_t)M_TOT*CC];    // x in fp16 (24MB)
__device__ __half g_wT16[3*HH*CC];            // W^T fp16: [mat][n][k]; Wq pre-scaled
__device__ __half g_q16[M_TOT*HH];            // pre-scaled by log2(e)/8 (via Wq)
__device__ __half g_k16[M_TOT*HH];
__device__ __half g_vT16[(size_t)BB*HH*TT];   // V transposed: [b][h][s]
__device__ float  g_pacc[(size_t)BB*NQT*KS*64*64];   // fp32 partials
__device__ float  g_pl[BB*NQT*KS*64];

// ---------------------------------------------------------------------------
// Kernel 0a: convert x to fp16 (compression pass — x read once from DRAM).
// ---------------------------------------------------------------------------
__global__ __launch_bounds__(256)
void cvtx_kernel(const float* __restrict__ x) {
    size_t i = ((size_t)blockIdx.x * 256 + threadIdx.x) * 8;
    float4 a = *(const float4*)(x + i);
    float4 b = *(const float4*)(x + i + 4);
    __half2 h0 = __floats2half2_rn(a.x, a.y);
    __half2 h1 = __floats2half2_rn(a.z, a.w);
    __half2 h2 = __floats2half2_rn(b.x, b.y);
    __half2 h3 = __floats2half2_rn(b.z, b.w);
    uint4 o = make_uint4(*(uint32_t*)&h0, *(uint32_t*)&h1,
                         *(uint32_t*)&h2, *(uint32_t*)&h3);
    *(uint4*)&g_x16[i] = o;
}

// ---------------------------------------------------------------------------
// Kernel 0b: convert + transpose W -> g_wT16[mat][n][k]; fold log2(e)/8 into Wq.
// ---------------------------------------------------------------------------
__global__ __launch_bounds__(256)
void cvtw_kernel(const float* __restrict__ Wk,
                 const float* __restrict__ Wq,
                 const float* __restrict__ Wv) {
    const int mat = blockIdx.y;
    const float* W = (mat == 0) ? Wk : ((mat == 1) ? Wq : Wv);
    const float scale = (mat == 1) ? 0.18033688011112042f : 1.0f;
    for (int idx = blockIdx.x * 256 + threadIdx.x; idx < CC * HH; idx += gridDim.x * 256) {
        int k = idx >> 6, n = idx & 63;
        g_wT16[(mat * HH + n) * CC + k] = __float2half(W[idx] * scale);
    }
}

// ---------------------------------------------------------------------------
// Kernel 1: QKV projection (R14 configuration — fp16 m16n8k16 + ldmatrix,
// CTA tile 128x64, kc=64, cp.async double-buffered).
// ---------------------------------------------------------------------------
#define PROJ_SMEM ((2*128*32 + 2*64*32) * 4)   // 48KB

__global__ __launch_bounds__(256)
void proj_kernel() {
    extern __shared__ uint32_t smu[];
    const uint32_t sb = smem_u32(smu);
    const int XB0 = 0;            // [2][4096 u32]
    const int WB0 = 8192;         // [2][2048 u32]

    const int mat  = blockIdx.y;
    const int m0   = blockIdx.x * 128;
    const int tid  = threadIdx.x;
    const int wid  = tid >> 5;
    const int lane = tid & 31;
    const int g    = lane >> 2;
    const int t    = lane & 3;
    const int ms   = wid >> 1;
    const int nn   = (wid & 1) * 32;

    const int lsw  = (lane & 7) << 2;
    const int bkh  = ((lane >> 3) & 1) << 2;
    const int brow0 = nn + ((lane >> 4) << 3) + (lane & 7);
    const int am   = lane >> 3;
    const int akh  = (am >> 1) << 2;
    const int arow0 = ms * 32 + ((am & 1) << 3) + (lane & 7);

    const __half* xp = g_x16;
    const __half* wp = g_wT16 + (size_t)mat * HH * CC;

    const int xrow = tid >> 1;
    const int xc0  = (tid & 1) * 4;
    const int wrow = tid >> 2;
    const int wc0  = (tid & 3) * 2;

    float oc[2][4][4];
#pragma unroll
    for (int mt = 0; mt < 2; mt++)
#pragma unroll
        for (int i = 0; i < 4; i++)
#pragma unroll
            for (int j = 0; j < 4; j++) oc[mt][i][j] = 0.f;

    {
#pragma unroll
        for (int it = 0; it < 4; it++) {
            int c = xc0 + it;
            uint32_t sw = (uint32_t)((c * 4) ^ ((xrow & 7) << 2));
            CP16(sb + (XB0 + xrow * 32 + sw) * 4, xp + (size_t)(m0 + xrow) * CC + c * 8);
        }
#pragma unroll
        for (int it = 0; it < 2; it++) {
            int c = wc0 + it;
            uint32_t sw = (uint32_t)((c * 4) ^ ((wrow & 7) << 2));
            CP16(sb + (WB0 + wrow * 32 + sw) * 4, wp + (size_t)wrow * CC + c * 8);
        }
        CP_COMMIT();
    }

    int buf = 0;
    for (int k0 = 0; k0 < CC; k0 += 64) {
        CP_WAIT0();
        __syncthreads();

        if (k0 + 64 < CC) {
            const int xb = XB0 + (buf ^ 1) * 4096;
            const int wb = WB0 + (buf ^ 1) * 2048;
#pragma unroll
            for (int it = 0; it < 4; it++) {
                int c = xc0 + it;
                uint32_t sw = (uint32_t)((c * 4) ^ ((xrow & 7) << 2));
                CP16(sb + (xb + xrow * 32 + sw) * 4,
                     xp + (size_t)(m0 + xrow) * CC + k0 + 64 + c * 8);
            }
#pragma unroll
            for (int it = 0; it < 2; it++) {
                int c = wc0 + it;
                uint32_t sw = (uint32_t)((c * 4) ^ ((wrow & 7) << 2));
                CP16(sb + (wb + wrow * 32 + sw) * 4,
                     wp + (size_t)wrow * CC + k0 + 64 + c * 8);
            }
            CP_COMMIT();
        }

        const int xb = XB0 + buf * 4096;
        const int wb = WB0 + buf * 2048;
#pragma unroll
        for (int kk = 0; kk < 4; kk++) {
            uint32_t a0v[4], a1v[4], bv[8];
            uint32_t cuA = (uint32_t)((kk * 8 + akh) ^ lsw);
            ldsm4(a0v, sb + (xb + arow0 * 32 + cuA) * 4);
            ldsm4(a1v, sb + (xb + (arow0 + 16) * 32 + cuA) * 4);
            uint32_t cuB = (uint32_t)((kk * 8 + bkh) ^ lsw);
            ldsm4(bv,     sb + (wb + brow0 * 32 + cuB) * 4);
            ldsm4(bv + 4, sb + (wb + (brow0 + 16) * 32 + cuB) * 4);
#pragma unroll
            for (int nt = 0; nt < 4; nt++) {
                mma16(oc[0][nt], a0v[0], a0v[1], a0v[2], a0v[3], bv[2*nt], bv[2*nt+1]);
                mma16(oc[1][nt], a1v[0], a1v[1], a1v[2], a1v[3], bv[2*nt], bv[2*nt+1]);
            }
        }
        buf ^= 1;
    }

    if (mat < 2) {
        __half* out16 = (mat == 0) ? g_k16 : g_q16;
#pragma unroll
        for (int mt = 0; mt < 2; mt++) {
            int r0 = m0 + ms * 32 + mt * 16 + g;
#pragma unroll
            for (int nt = 0; nt < 4; nt++) {
                int col = nn + nt * 8 + 2 * t;
                __half2 h0 = __floats2half2_rn(oc[mt][nt][0], oc[mt][nt][1]);
                __half2 h1 = __floats2half2_rn(oc[mt][nt][2], oc[mt][nt][3]);
                *(__half2*)&out16[(size_t)r0 * HH + col]       = h0;
                *(__half2*)&out16[(size_t)(r0 + 8) * HH + col] = h1;
            }
        }
    } else {
        __syncthreads();
        __half* Vt = (__half*)smu;   // [64][136] halves
#pragma unroll
        for (int mt = 0; mt < 2; mt++) {
            int lr = ms * 32 + mt * 16 + g;
#pragma unroll
            for (int nt = 0; nt < 4; nt++) {
                int col = nn + nt * 8 + 2 * t;
                Vt[col * 136 + lr]           = __float2half(oc[mt][nt][0]);
                Vt[(col + 1) * 136 + lr]     = __float2half(oc[mt][nt][1]);
                Vt[col * 136 + lr + 8]       = __float2half(oc[mt][nt][2]);
                Vt[(col + 1) * 136 + lr + 8] = __float2half(oc[mt][nt][3]);
            }
        }
        __syncthreads();
        const int batch = m0 >> 12;
        const int s0    = m0 & (TT - 1);
        const int row = tid >> 2;
        const int seg = tid & 3;
#pragma unroll
        for (int it = 0; it < 4; it++) {
            int off = seg * 32 + it * 8;
            uint4 v = *(uint4*)&Vt[row * 136 + off];
            *(uint4*)&g_vT16[((size_t)(batch * HH + row)) * TT + s0 + off] = v;
        }
    }
}

// ---------------------------------------------------------------------------
// Kernel 2: fp16 flash attention, FA2 register path. 128 threads / 4 warps;
// each warp owns a full 16x64 S slab, so GEMM1's C frags convert in-register
// to GEMM2's A frags (P never touches smem; no post-softmax barrier; row
// sums complete within a warp). K/V^T double-buffered cp.async; 1 sync/chunk.
// smem u32: KB[2][2048] | VB[2][2048] | Q[2048] = 40KB -> 4 CTAs/SM.
// ---------------------------------------------------------------------------
#define KB_OFF 0
#define VB_OFF 4096
#define QB_OFF 8192
#define ATTN_SMEM (10240 * 4)

__global__ __launch_bounds__(128, 4)
void attn_kernel() {
    extern __shared__ uint32_t smu[];
    const uint32_t sb = smem_u32(smu);

    const int tid  = threadIdx.x;
    const int wid  = tid >> 5;
    const int lane = tid & 31;
    const int g    = lane >> 2;
    const int t    = lane & 3;
    const int ms   = wid;                // 0..3: 16-row slab
    const int r0   = ms * 16 + g;

    // ldmatrix lane params
    const int lsw  = (lane & 7) << 2;
    const int bkh  = ((lane >> 3) & 1) << 2;
    const int brow = ((lane >> 4) << 3) + (lane & 7);   // + nb + {0,16}
    const int am   = lane >> 3;
    const int akh  = (am >> 1) << 2;
    const int arow0 = ms * 16 + ((am & 1) << 3) + (lane & 7);

    const int b     = blockIdx.y;
    const int qt    = NQT - 1 - (blockIdx.x >> 2);   // heavy tiles first
    const int split = blockIdx.x & (KS - 1);
    const int q0    = qt * 64;
    const int nch   = qt + 1;
    const int lo    = (split * nch) / KS;
    const int hi    = ((split + 1) * nch) / KS;
    const size_t slot = (size_t)(b * NQT + qt) * KS + split;
    float* pa = g_pacc + slot * 4096;

    if (lo >= hi) {
        float4 z = make_float4(0.f, 0.f, 0.f, 0.f);
        for (int e = tid; e < 1024; e += 128) ((float4*)pa)[e] = z;
        if (tid < 64) g_pl[slot * 64 + tid] = 0.f;
        return;
    }

    const __half* qp  = g_q16 + (size_t)b * TT * HH;
    const __half* kp  = g_k16 + (size_t)b * TT * HH;
    const __half* vtp = g_vT16 + (size_t)b * HH * TT;

    // staging: 64 rows x 8 16B-chunks; 128 thr -> 2 thr/row, 4 chunks each
    const int srow = tid >> 1;
    const int sc0  = (tid & 1) * 4;
    const int ssw  = (srow & 7) << 2;

    {
        const int s0 = lo * 64;
#pragma unroll
        for (int it = 0; it < 4; it++) {
            int c = sc0 + it;
            uint32_t sw = (uint32_t)((c * 4) ^ ssw);
            CP16(sb + (KB_OFF + srow * 32 + sw) * 4, kp + (size_t)(s0 + srow) * HH + c * 8);
            CP16(sb + (VB_OFF + srow * 32 + sw) * 4, vtp + (size_t)srow * TT + s0 + c * 8);
            CP16(sb + (QB_OFF + srow * 32 + sw) * 4, qp + (size_t)(q0 + srow) * HH + c * 8);
        }
        CP_COMMIT();
    }
    CP_WAIT0();
    __syncthreads();

    // Q fragments via ldmatrix
    uint32_t qa[4][4];
#pragma unroll
    for (int kk = 0; kk < 4; kk++) {
        uint32_t cu = (uint32_t)((kk * 8 + akh) ^ lsw);
        ldsm4(qa[kk], sb + (QB_OFF + arow0 * 32 + cu) * 4);
    }

    float oc[8][4];
#pragma unroll
    for (int i = 0; i < 8; i++)
#pragma unroll
        for (int j = 0; j < 4; j++) oc[i][j] = 0.f;
    float lr0 = 0.f, lr1 = 0.f;

    int buf = 0;
    for (int ck = lo; ck < hi; ck++) {
        if (ck + 1 < hi) {
            const int s1 = (ck + 1) * 64;
            const int kb = KB_OFF + (buf ^ 1) * 2048;
            const int vb = VB_OFF + (buf ^ 1) * 2048;
#pragma unroll
            for (int it = 0; it < 4; it++) {
                int c = sc0 + it;
                uint32_t sw = (uint32_t)((c * 4) ^ ssw);
                CP16(sb + (kb + srow * 32 + sw) * 4, kp + (size_t)(s1 + srow) * HH + c * 8);
                CP16(sb + (vb + srow * 32 + sw) * 4, vtp + (size_t)srow * TT + s1 + c * 8);
            }
        }
        CP_COMMIT();

        const int kb = KB_OFF + buf * 2048;
        const int vb = VB_OFF + buf * 2048;

        // GEMM1: S[16x64] = Q x K^T (8 n-tiles, 4 k16 steps)
        float sc[8][4];
#pragma unroll
        for (int i = 0; i < 8; i++)
#pragma unroll
            for (int j = 0; j < 4; j++) sc[i][j] = 0.f;
#pragma unroll
        for (int kk = 0; kk < 4; kk++) {
            uint32_t bv[16];
            uint32_t cu = (uint32_t)((kk * 8 + bkh) ^ lsw);
            ldsm4(bv,      sb + (kb + brow * 32 + cu) * 4);
            ldsm4(bv + 4,  sb + (kb + (brow + 16) * 32 + cu) * 4);
            ldsm4(bv + 8,  sb + (kb + (brow + 32) * 32 + cu) * 4);
            ldsm4(bv + 12, sb + (kb + (brow + 48) * 32 + cu) * 4);
#pragma unroll
            for (int nt = 0; nt < 8; nt++)
                mma16(sc[nt], qa[kk][0], qa[kk][1], qa[kk][2], qa[kk][3],
                      bv[2*nt], bv[2*nt+1]);
        }

        // softmax: P = exp2(S) packed straight into GEMM2 A-fragments
        const bool diag = (ck == qt);
        uint32_t pA[4][4];
#pragma unroll
        for (int nt = 0; nt < 8; nt++) {
            int cl = nt * 8 + 2 * t;
            float p0 = ex2(sc[nt][0]);
            float p1 = ex2(sc[nt][1]);
            float p2 = ex2(sc[nt][2]);
            float p3 = ex2(sc[nt][3]);
            if (diag) {
                if (cl > r0)         p0 = 0.f;
                if (cl + 1 > r0)     p1 = 0.f;
                if (cl > r0 + 8)     p2 = 0.f;
                if (cl + 1 > r0 + 8) p3 = 0.f;
            }
            __half2 h01 = __floats2half2_rn(p0, p1);
            __half2 h23 = __floats2half2_rn(p2, p3);
            float2 f01 = __half22float2(h01);
            float2 f23 = __half22float2(h23);
            lr0 += f01.x + f01.y;
            lr1 += f23.x + f23.y;
            // C(nt) -> A(kk = nt>>1): even nt = k-lo half, odd nt = k-hi half
            pA[nt >> 1][(nt & 1) ? 2 : 0] = *(uint32_t*)&h01;
            pA[nt >> 1][(nt & 1) ? 3 : 1] = *(uint32_t*)&h23;
        }

        // GEMM2: O[16x64] += P x V (B = V^T, 8 h-tiles, 4 k16 steps)
#pragma unroll
        for (int kk = 0; kk < 4; kk++) {
            uint32_t bv[16];
            uint32_t cu = (uint32_t)((kk * 8 + bkh) ^ lsw);
            ldsm4(bv,      sb + (vb + brow * 32 + cu) * 4);
            ldsm4(bv + 4,  sb + (vb + (brow + 16) * 32 + cu) * 4);
            ldsm4(bv + 8,  sb + (vb + (brow + 32) * 32 + cu) * 4);
            ldsm4(bv + 12, sb + (vb + (brow + 48) * 32 + cu) * 4);
#pragma unroll
            for (int nt = 0; nt < 8; nt++)
                mma16(oc[nt], pA[kk][0], pA[kk][1], pA[kk][2], pA[kk][3],
                      bv[2*nt], bv[2*nt+1]);
        }

        CP_WAIT0();
        __syncthreads();
        buf ^= 1;
    }

    // row sums complete within warp: reduce over t lanes
    lr0 += __shfl_xor_sync(0xffffffffu, lr0, 1);
    lr0 += __shfl_xor_sync(0xffffffffu, lr0, 2);
    lr1 += __shfl_xor_sync(0xffffffffu, lr1, 1);
    lr1 += __shfl_xor_sync(0xffffffffu, lr1, 2);
    if (t == 0) {
        g_pl[slot * 64 + r0]     = lr0;
        g_pl[slot * 64 + r0 + 8] = lr1;
    }

    // write partials
#pragma unroll
    for (int nt = 0; nt < 8; nt++) {
        int col = nt * 8 + 2 * t;
        *(float2*)&pa[r0 * 64 + col]       = make_float2(oc[nt][0], oc[nt][1]);
        *(float2*)&pa[(r0 + 8) * 64 + col] = make_float2(oc[nt][2], oc[nt][3]);
    }
}

// ---------------------------------------------------------------------------
// Kernel 3: merge key-split partials and normalize. grid (NQT*2, BB).
// ---------------------------------------------------------------------------
__global__ __launch_bounds__(256)
void combine_kernel(float* __restrict__ out) {
    const int qt   = blockIdx.x >> 1;
    const int half = blockIdx.x & 1;
    const int b    = blockIdx.y;
    const int tid  = threadIdx.x;
    const size_t base = (size_t)(b * NQT + qt) * KS;
    const int e0 = half * 512;

    __shared__ float ls[32];
    if (tid < 32) {
        int row = half * 32 + tid;
        float s = 0.f;
#pragma unroll
        for (int sp = 0; sp < KS; sp++) s += g_pl[(base + sp) * 64 + row];
        ls[tid] = 1.0f / s;
    }
    __syncthreads();

    for (int e = tid; e < 512; e += 256) {
        const int row = (e0 + e) >> 4;
        float4 a = make_float4(0.f, 0.f, 0.f, 0.f);
#pragma unroll
        for (int sp = 0; sp < KS; sp++) {
            float4 v = ((const float4*)(g_pacc + (base + sp) * 4096))[e0 + e];
            a.x += v.x; a.y += v.y; a.z += v.z; a.w += v.w;
        }
        const float inv = ls[row - half * 32];
        a.x *= inv; a.y *= inv; a.z *= inv; a.w *= inv;
        *(float4*)&out[((size_t)b * TT + qt * 64 + row) * HH + ((e0 + e) & 15) * 4] = a;
    }
}

extern "C" void kernel_launch(void* const* d_in, const int* in_sizes, int n_in,
                              void* d_out, int out_size) {
    const float* x  = (const float*)d_in[0];
    const float* Wk = (const float*)d_in[1];
    const float* Wq = (const float*)d_in[2];
    const float* Wv = (const float*)d_in[3];
    float* out = (float*)d_out;

    cvtx_kernel<<<M_TOT * CC / (256 * 8), 256>>>(x);
    cvtw_kernel<<<dim3(8, 3), 256>>>(Wk, Wq, Wv);

    cudaFuncSetAttribute(proj_kernel,
                         cudaFuncAttributeMaxDynamicSharedMemorySize, PROJ_SMEM);
    proj_kernel<<<dim3(M_TOT / 128, 3), 256, PROJ_SMEM>>>();

    cudaFuncSetAttribute(attn_kernel,
                         cudaFuncAttributeMaxDynamicSharedMemorySize, ATTN_SMEM);
    attn_kernel<<<dim3(NQT * KS, BB), 128, ATTN_SMEM>>>();

    combine_kernel<<<dim3(NQT * 2, BB), 256>>>(out);
}